// round 15
// baseline (speedup 1.0000x reference)
#include <cuda_runtime.h>
#include <cuda_fp16.h>
#include <cstdint>
#include <cstring>

// ---------------------------------------------------------------------------
// Problem constants (DIMS = [1024, 2048, 2048, 51], B=16, P=1024)
// ---------------------------------------------------------------------------
#define MROWS 16384
#define D0    1024
#define D1    2048
#define D2    2048
#define NCLS  51
#define NPAD  64

// ---------------------------------------------------------------------------
// Device-global scratch (allocation-free rule)
// ---------------------------------------------------------------------------
__device__ __half g_Xh [MROWS * D0];          // 32 MB
__device__ __half g_W0h[D1 * D0];             //  4 MB
__device__ __half g_W1h[D2 * D1];             //  8 MB
__device__ __half g_W2h[NPAD * D2];           // 256 KB (rows 51..63 zero)
__device__ __half g_H1 [(size_t)MROWS * D1];  // 64 MB
__device__ __half g_H2 [(size_t)MROWS * D2];  // 64 MB

__device__ __forceinline__ unsigned smem_u32(const void* p) {
    return (unsigned)__cvta_generic_to_shared(p);
}

// ---------------------------------------------------------------------------
// fp32 -> fp16 converts: 8 elems/thread, 2x float4 load -> 1x 16B store
// ---------------------------------------------------------------------------
struct __align__(16) Half8 { __half2 a, b, c, d; };

template<int WHICH>
__global__ void f2h_kernel(const float* __restrict__ in, int n) {
    __half* __restrict__ out = (WHICH == 0) ? g_Xh : (WHICH == 1) ? g_W0h : g_W1h;
    int i = (blockIdx.x * blockDim.x + threadIdx.x) * 8;
    if (i < n) {
        float4 v0 = *reinterpret_cast<const float4*>(in + i);
        float4 v1 = *reinterpret_cast<const float4*>(in + i + 4);
        Half8 o;
        o.a = __floats2half2_rn(v0.x, v0.y);
        o.b = __floats2half2_rn(v0.z, v0.w);
        o.c = __floats2half2_rn(v1.x, v1.y);
        o.d = __floats2half2_rn(v1.z, v1.w);
        *reinterpret_cast<Half8*>(out + i) = o;
    }
}

// W2 [51,2048] fp32 -> g_W2h [64,2048] fp16, rows 51..63 zeroed
__global__ void w2pad_kernel(const float* __restrict__ W2) {
    int i = (blockIdx.x * blockDim.x + threadIdx.x) * 2;
    if (i < NPAD * D2) {
        int row = i / D2;
        float a = 0.f, b = 0.f;
        if (row < NCLS) {
            a = W2[(size_t)row * D2 + (i % D2)];
            b = W2[(size_t)row * D2 + (i % D2) + 1];
        }
        *reinterpret_cast<__half2*>(&g_W2h[i]) = __floats2half2_rn(a, b);
    }
}

// ---------------------------------------------------------------------------
// fp16 mma.sync GEMM, 3-stage cp.async pipeline, BK=64, fused bias (+relu).
//   C[m,n] = act( sum_k A[m,k] * W[n,k] + bias[n] )
// Per-warp tile is the proven 64 x 32 (16 HMMA / 6 LDSM per k16).
//   LAYER 1/2: CTA 256 x 128, 512 threads = 16 warps (4 M x 4 N)
//              -> halves W-operand L2 re-reads vs 128x128 tiles
//   LAYER 3  : CTA 128 x 64,  256 threads =  8 warps (2 M x 4 N)
// Next-stage cp.async chunks are INTERLEAVED between the four k16 MMA groups
// so the first ldmatrix is never blocked by an LSU burst, yet loads enter
// flight well before the iteration ends. One commit per iteration (empty at
// the tail) keeps wait_group semantics exact.
// ---------------------------------------------------------------------------
#define BK     64
#define SPAD   72       // halfs per smem row (144B stride; conflict-free LDSM)
#define NSTAGE 3

template<int LAYER>
__global__ void __launch_bounds__(512, 1)
gemm_mma(const float* __restrict__ bias, float* __restrict__ out) {
    constexpr int K   = (LAYER == 1) ? D0 : D1;
    constexpr int BM  = (LAYER == 3) ? 128 : 256;
    constexpr int BN  = (LAYER == 3) ? 64 : 128;
    constexpr int NT  = (LAYER == 3) ? 256 : 512;  // threads
    constexpr int MW  = (LAYER == 3) ? 2 : 4;      // warps in M
    constexpr int WN  = BN / 4;            // warp N tile: 32 or 16
    constexpr int NJ  = WN / 8;            // mma count in N: 4 or 2
    constexpr int NB  = WN / 16;           // B ldmatrix.x4 count: 2 or 1
    constexpr int KT  = K / BK;
    constexpr int STAGE_H = (BM + BN) * SPAD;      // halfs per stage
    constexpr int CPT = (BM + BN) * 8 / NT;        // 16B chunks per thread (6)
    constexpr int CPS = (CPT + 3) / 4;             // chunks per k16 step (2)

    const __half* __restrict__ A = (LAYER == 1) ? g_Xh : (LAYER == 2) ? g_H1 : g_H2;
    const __half* __restrict__ W = (LAYER == 1) ? g_W0h : (LAYER == 2) ? g_W1h : g_W2h;

    extern __shared__ __half smem[];

    const int tid  = threadIdx.x;
    const int lane = tid & 31;
    const int wid  = tid >> 5;
    const int warp_m = wid & (MW - 1);
    const int warp_n = wid / MW;
    const int m0 = blockIdx.y * BM;
    const int n0 = blockIdx.x * BN;

    float acc[4][NJ][4];
    #pragma unroll
    for (int mi = 0; mi < 4; mi++)
        #pragma unroll
        for (int nj = 0; nj < NJ; nj++)
            #pragma unroll
            for (int c = 0; c < 4; c++) acc[mi][nj][c] = 0.f;

    // --- single-chunk issuer (16B cp.async), chunk id = tid + i*NT ---
    auto load_chunk = [&](int s, int kt, int i) {
        const int k0 = kt * BK;
        __half* dst = smem + s * STAGE_H;
        int idx = tid + i * NT;
        int row = idx >> 3;             // 0..BM+BN-1 (8 chunks per 128B row)
        int ch  = idx & 7;
        const __half* src;
        __half* d;
        if (row < BM) {
            src = A + (size_t)(m0 + row) * K + k0 + ch * 8;
            d   = dst + row * SPAD + ch * 8;
        } else {
            int r = row - BM;
            src = W + (size_t)(n0 + r) * K + k0 + ch * 8;
            d   = dst + (BM + r) * SPAD + ch * 8;
        }
        asm volatile("cp.async.cg.shared.global [%0], [%1], 16;\n"
                     :: "r"(smem_u32(d)), "l"(src));
    };

    auto load_stage = [&](int s, int kt) {
        #pragma unroll
        for (int i = 0; i < CPT; i++) load_chunk(s, kt, i);
        asm volatile("cp.async.commit_group;\n" ::: "memory");
    };

    // prologue: fill 2 stages (groups G0, G1)
    load_stage(0, 0);
    load_stage(1, 1);

    int s = 0;           // stage being consumed (kt % 3)
    int sl = 2;          // stage to load this iteration ((kt+2) % 3)
    for (int kt = 0; kt < KT; kt++) {
        // one group per iteration -> keeping <=1 pending retires G(kt) = stage s
        asm volatile("cp.async.wait_group 1;\n" ::: "memory");
        __syncthreads();

        const bool do_load = (kt + 2 < KT);
        const __half* sA = smem + s * STAGE_H;
        const __half* sB = sA + BM * SPAD;

        #pragma unroll
        for (int ks = 0; ks < 4; ks++) {
            const int k16 = ks * 16;
            unsigned a[4][4];
            #pragma unroll
            for (int mi = 0; mi < 4; mi++) {
                int row = warp_m * 64 + mi * 16 + (lane & 15);
                int kh  = k16 + ((lane & 16) ? 8 : 0);
                asm volatile(
                    "ldmatrix.sync.aligned.m8n8.x4.shared.b16 {%0,%1,%2,%3}, [%4];\n"
                    : "=r"(a[mi][0]), "=r"(a[mi][1]), "=r"(a[mi][2]), "=r"(a[mi][3])
                    : "r"(smem_u32(&sA[row * SPAD + kh])));
            }
            unsigned b[NJ][2];
            #pragma unroll
            for (int ni = 0; ni < NB; ni++) {
                int nrow = warp_n * WN + ni * 16 + ((lane & 16) ? 8 : 0) + (lane & 7);
                int kh   = k16 + ((lane & 8) ? 8 : 0);
                unsigned r0, r1, r2, r3;
                asm volatile(
                    "ldmatrix.sync.aligned.m8n8.x4.shared.b16 {%0,%1,%2,%3}, [%4];\n"
                    : "=r"(r0), "=r"(r1), "=r"(r2), "=r"(r3)
                    : "r"(smem_u32(&sB[nrow * SPAD + kh])));
                b[ni * 2 + 0][0] = r0; b[ni * 2 + 0][1] = r1;
                b[ni * 2 + 1][0] = r2; b[ni * 2 + 1][1] = r3;
            }
            #pragma unroll
            for (int mi = 0; mi < 4; mi++)
                #pragma unroll
                for (int nj = 0; nj < NJ; nj++) {
                    asm volatile(
                        "mma.sync.aligned.m16n8k16.row.col.f32.f16.f16.f32 "
                        "{%0,%1,%2,%3}, {%4,%5,%6,%7}, {%8,%9}, {%0,%1,%2,%3};\n"
                        : "+f"(acc[mi][nj][0]), "+f"(acc[mi][nj][1]),
                          "+f"(acc[mi][nj][2]), "+f"(acc[mi][nj][3])
                        : "r"(a[mi][0]), "r"(a[mi][1]), "r"(a[mi][2]), "r"(a[mi][3]),
                          "r"(b[nj][0]), "r"(b[nj][1]));
                }
            // interleaved next-stage loads hide under tensor execution
            if (do_load) {
                #pragma unroll
                for (int i = ks * CPS; i < (ks + 1) * CPS && i < CPT; i++)
                    load_chunk(sl, kt + 2, i);
            }
        }
        // exactly one commit per iteration (holds loaded chunks, or empty)
        asm volatile("cp.async.commit_group;\n" ::: "memory");

        s  = (s  == NSTAGE - 1) ? 0 : s + 1;
        sl = (sl == NSTAGE - 1) ? 0 : sl + 1;
    }

    // --- epilogue: bias + activation + store ---
    #pragma unroll
    for (int mi = 0; mi < 4; mi++) {
        #pragma unroll
        for (int nj = 0; nj < NJ; nj++) {
            int col = n0 + warp_n * WN + nj * 8 + (lane & 3) * 2;
            #pragma unroll
            for (int h = 0; h < 2; h++) {
                int row = m0 + warp_m * 64 + mi * 16 + (lane >> 2) + h * 8;
                float v0 = acc[mi][nj][h * 2 + 0];
                float v1 = acc[mi][nj][h * 2 + 1];
                if (LAYER == 3) {
                    if (col < NCLS)
                        out[(size_t)row * NCLS + col] = v0 + bias[col];
                    if (col + 1 < NCLS)
                        out[(size_t)row * NCLS + col + 1] = v1 + bias[col + 1];
                } else {
                    __half* __restrict__ H = (LAYER == 1) ? g_H1 : g_H2;
                    float r0 = fmaxf(v0 + bias[col], 0.f);
                    float r1 = fmaxf(v1 + bias[col + 1], 0.f);
                    *reinterpret_cast<__half2*>(&H[(size_t)row * D1 + col]) =
                        __floats2half2_rn(r0, r1);
                }
            }
        }
    }
}

// ---------------------------------------------------------------------------
// Launch
// ---------------------------------------------------------------------------
extern "C" void kernel_launch(void* const* d_in, const int* in_sizes, int n_in,
                              void* d_out, int out_size) {
    const float *X = nullptr, *W0 = nullptr, *b0 = nullptr, *W1 = nullptr,
                *b1 = nullptr, *W2 = nullptr, *b2 = nullptr;
    for (int i = 0; i < n_in; i++) {
        int s = in_sizes[i];
        if      (s == MROWS * D0) X  = (const float*)d_in[i];
        else if (s == D1 * D0)    W0 = (const float*)d_in[i];
        else if (s == D2 * D1)    W1 = (const float*)d_in[i];
        else if (s == NCLS * D2)  W2 = (const float*)d_in[i];
        else if (s == NCLS)       b2 = (const float*)d_in[i];
        else if (s == D1) {
            if (!b0) b0 = (const float*)d_in[i];
            else if (!b1) b1 = (const float*)d_in[i];
        }
    }
    float* out = (float*)d_out;

    const int smem12 = NSTAGE * (256 + 128) * SPAD * 2;   // 165888 B
    const int smem3  = NSTAGE * (128 + 64)  * SPAD * 2;   // 82944 B
    cudaFuncSetAttribute(gemm_mma<1>, cudaFuncAttributeMaxDynamicSharedMemorySize, smem12);
    cudaFuncSetAttribute(gemm_mma<2>, cudaFuncAttributeMaxDynamicSharedMemorySize, smem12);
    cudaFuncSetAttribute(gemm_mma<3>, cudaFuncAttributeMaxDynamicSharedMemorySize, smem3);

    // converts (w2pad first so the ncu -s window lands on a GEMM launch)
    { int n = NPAD * D2;  w2pad_kernel<<<(n / 2 + 255) / 256, 256>>>(W2); }
    { int n = MROWS * D0; f2h_kernel<0><<<(n / 8 + 255) / 256, 256>>>(X, n); }
    { int n = D1 * D0;    f2h_kernel<1><<<(n / 8 + 255) / 256, 256>>>(W0, n); }
    { int n = D2 * D1;    f2h_kernel<2><<<(n / 8 + 255) / 256, 256>>>(W1, n); }

    // Layer 1: H1 = relu(X @ W0^T + b0)   CTA 256x128, 512 thr
    gemm_mma<1><<<dim3(D1 / 128, MROWS / 256), 512, smem12>>>(b0, nullptr);
    // Layer 2: H2 = relu(H1 @ W1^T + b1)  CTA 256x128, 512 thr
    gemm_mma<2><<<dim3(D2 / 128, MROWS / 256), 512, smem12>>>(b1, nullptr);
    // Layer 3: out = H2 @ W2^T + b2  (N padded to 64, cols >= 51 dropped)
    gemm_mma<3><<<dim3(1, MROWS / 128), 256, smem3>>>(b2, out);
}

// round 16
// speedup vs baseline: 1.0356x; 1.0356x over previous
#include <cuda_runtime.h>
#include <cuda_fp16.h>
#include <cstdint>
#include <cstring>

// ---------------------------------------------------------------------------
// Problem constants (DIMS = [1024, 2048, 2048, 51], B=16, P=1024)
// ---------------------------------------------------------------------------
#define MROWS 16384
#define D0    1024
#define D1    2048
#define D2    2048
#define NCLS  51
#define NPAD  64

#define NX  (MROWS * D0)   // 16777216
#define NW0 (D1 * D0)      // 2097152
#define NW1 (D2 * D1)      // 4194304

// ---------------------------------------------------------------------------
// Device-global scratch (allocation-free rule)
// ---------------------------------------------------------------------------
__device__ __half g_Xh [NX];                  // 32 MB
__device__ __half g_W0h[NW0];                 //  4 MB
__device__ __half g_W1h[NW1];                 //  8 MB
__device__ __half g_W2h[NPAD * D2];           // 256 KB (rows 51..63 zero)
__device__ __half g_H1 [(size_t)MROWS * D1];  // 64 MB
__device__ __half g_H2 [(size_t)MROWS * D2];  // 64 MB

__device__ __forceinline__ unsigned smem_u32(const void* p) {
    return (unsigned)__cvta_generic_to_shared(p);
}

// ---------------------------------------------------------------------------
// Fused fp32->fp16 convert for X, W0, W1 in ONE kernel.
// 16 elems/thread: 4 independent float4 loads (MLP=4) -> 2 x 16B stores.
// Region select by chunk id; all sizes are multiples of 16.
// ---------------------------------------------------------------------------
struct __align__(16) Half8 { __half2 a, b, c, d; };

__global__ void f2h_all_kernel(const float* __restrict__ X,
                               const float* __restrict__ W0,
                               const float* __restrict__ W1) {
    const int t = blockIdx.x * blockDim.x + threadIdx.x;
    long i = (long)t * 16;
    const float* __restrict__ src;
    __half* __restrict__ dst;
    if (i < NX) {
        src = X; dst = g_Xh;
    } else if (i < NX + NW0) {
        src = W0; dst = g_W0h; i -= NX;
    } else if (i < NX + NW0 + NW1) {
        src = W1; dst = g_W1h; i -= (NX + NW0);
    } else {
        return;
    }
    float4 v0 = *reinterpret_cast<const float4*>(src + i);
    float4 v1 = *reinterpret_cast<const float4*>(src + i + 4);
    float4 v2 = *reinterpret_cast<const float4*>(src + i + 8);
    float4 v3 = *reinterpret_cast<const float4*>(src + i + 12);
    Half8 o0, o1;
    o0.a = __floats2half2_rn(v0.x, v0.y);
    o0.b = __floats2half2_rn(v0.z, v0.w);
    o0.c = __floats2half2_rn(v1.x, v1.y);
    o0.d = __floats2half2_rn(v1.z, v1.w);
    o1.a = __floats2half2_rn(v2.x, v2.y);
    o1.b = __floats2half2_rn(v2.z, v2.w);
    o1.c = __floats2half2_rn(v3.x, v3.y);
    o1.d = __floats2half2_rn(v3.z, v3.w);
    *reinterpret_cast<Half8*>(dst + i)     = o0;
    *reinterpret_cast<Half8*>(dst + i + 8) = o1;
}

// W2 [51,2048] fp32 -> g_W2h [64,2048] fp16, rows 51..63 zeroed
__global__ void w2pad_kernel(const float* __restrict__ W2) {
    int i = (blockIdx.x * blockDim.x + threadIdx.x) * 2;
    if (i < NPAD * D2) {
        int row = i / D2;
        float a = 0.f, b = 0.f;
        if (row < NCLS) {
            a = W2[(size_t)row * D2 + (i % D2)];
            b = W2[(size_t)row * D2 + (i % D2) + 1];
        }
        *reinterpret_cast<__half2*>(&g_W2h[i]) = __floats2half2_rn(a, b);
    }
}

// ---------------------------------------------------------------------------
// fp16 mma.sync GEMM, 3-stage cp.async pipeline, BK=64, fused bias (+relu).
//   C[m,n] = act( sum_k A[m,k] * W[n,k] + bias[n] )
// 256 threads = 8 warps (2 M x 4 N), warp tile 64 x (BN/4).
//   LAYER 1/2: CTA 128 x 128 (warp 64 x 32), occ 2
//   LAYER 3  : CTA 128 x 64  (warp 64 x 16)
// Next-stage cp.async chunks are INTERLEAVED between the four k16 MMA groups
// (2 chunks after each) so the first ldmatrix is never blocked by an LSU
// burst, yet loads enter flight well before the iteration ends. One group
// commit per iteration (empty at the tail) keeps wait_group semantics exact.
// (R14 configuration — empirical optimum; do not change without SASS data.)
// ---------------------------------------------------------------------------
#define BM     128
#define BK     64
#define SPAD   72       // halfs per smem row (144B stride; conflict-free LDSM)
#define NSTAGE 3

template<int LAYER>
__global__ void __launch_bounds__(256, 2)
gemm_mma(const float* __restrict__ bias, float* __restrict__ out) {
    constexpr int K  = (LAYER == 1) ? D0 : D1;
    constexpr int BN = (LAYER == 3) ? 64 : 128;
    constexpr int WN = BN / 4;             // warp N tile: 32 or 16
    constexpr int NJ = WN / 8;             // mma count in N: 4 or 2
    constexpr int NB = WN / 16;            // B ldmatrix.x4 count: 2 or 1
    constexpr int KT = K / BK;
    constexpr int STAGE_H = (BM + BN) * SPAD;      // halfs per stage
    constexpr int CPT = (BM + BN) * 8 / 256;       // 16B chunks per thread (8 or 6)
    constexpr int CPS = (CPT + 3) / 4;             // chunks per k16 step (2)

    const __half* __restrict__ A = (LAYER == 1) ? g_Xh : (LAYER == 2) ? g_H1 : g_H2;
    const __half* __restrict__ W = (LAYER == 1) ? g_W0h : (LAYER == 2) ? g_W1h : g_W2h;

    extern __shared__ __half smem[];

    const int tid  = threadIdx.x;
    const int lane = tid & 31;
    const int wid  = tid >> 5;
    const int warp_m = wid & 1;
    const int warp_n = wid >> 1;
    const int m0 = blockIdx.y * BM;
    const int n0 = blockIdx.x * BN;

    float acc[4][NJ][4];
    #pragma unroll
    for (int mi = 0; mi < 4; mi++)
        #pragma unroll
        for (int nj = 0; nj < NJ; nj++)
            #pragma unroll
            for (int c = 0; c < 4; c++) acc[mi][nj][c] = 0.f;

    // --- single-chunk issuer (16B cp.async), chunk id = tid + i*256 ---
    auto load_chunk = [&](int s, int kt, int i) {
        const int k0 = kt * BK;
        __half* dst = smem + s * STAGE_H;
        int idx = tid + i * 256;
        int row = idx >> 3;             // 0..BM+BN-1 (8 chunks per 128B row)
        int ch  = idx & 7;
        const __half* src;
        __half* d;
        if (row < BM) {
            src = A + (size_t)(m0 + row) * K + k0 + ch * 8;
            d   = dst + row * SPAD + ch * 8;
        } else {
            int r = row - BM;
            src = W + (size_t)(n0 + r) * K + k0 + ch * 8;
            d   = dst + (BM + r) * SPAD + ch * 8;
        }
        asm volatile("cp.async.cg.shared.global [%0], [%1], 16;\n"
                     :: "r"(smem_u32(d)), "l"(src));
    };

    auto load_stage = [&](int s, int kt) {
        #pragma unroll
        for (int i = 0; i < CPT; i++) load_chunk(s, kt, i);
        asm volatile("cp.async.commit_group;\n" ::: "memory");
    };

    // prologue: fill 2 stages (groups G0, G1)
    load_stage(0, 0);
    load_stage(1, 1);

    int s = 0;           // stage being consumed (kt % 3)
    int sl = 2;          // stage to load this iteration ((kt+2) % 3)
    for (int kt = 0; kt < KT; kt++) {
        // one group per iteration -> keeping <=1 pending retires G(kt) = stage s
        asm volatile("cp.async.wait_group 1;\n" ::: "memory");
        __syncthreads();

        const bool do_load = (kt + 2 < KT);
        const __half* sA = smem + s * STAGE_H;
        const __half* sB = sA + BM * SPAD;

        #pragma unroll
        for (int ks = 0; ks < 4; ks++) {
            const int k16 = ks * 16;
            unsigned a[4][4];
            #pragma unroll
            for (int mi = 0; mi < 4; mi++) {
                int row = warp_m * 64 + mi * 16 + (lane & 15);
                int kh  = k16 + ((lane & 16) ? 8 : 0);
                asm volatile(
                    "ldmatrix.sync.aligned.m8n8.x4.shared.b16 {%0,%1,%2,%3}, [%4];\n"
                    : "=r"(a[mi][0]), "=r"(a[mi][1]), "=r"(a[mi][2]), "=r"(a[mi][3])
                    : "r"(smem_u32(&sA[row * SPAD + kh])));
            }
            unsigned b[NJ][2];
            #pragma unroll
            for (int ni = 0; ni < NB; ni++) {
                int nrow = warp_n * WN + ni * 16 + ((lane & 16) ? 8 : 0) + (lane & 7);
                int kh   = k16 + ((lane & 8) ? 8 : 0);
                unsigned r0, r1, r2, r3;
                asm volatile(
                    "ldmatrix.sync.aligned.m8n8.x4.shared.b16 {%0,%1,%2,%3}, [%4];\n"
                    : "=r"(r0), "=r"(r1), "=r"(r2), "=r"(r3)
                    : "r"(smem_u32(&sB[nrow * SPAD + kh])));
                b[ni * 2 + 0][0] = r0; b[ni * 2 + 0][1] = r1;
                b[ni * 2 + 1][0] = r2; b[ni * 2 + 1][1] = r3;
            }
            #pragma unroll
            for (int mi = 0; mi < 4; mi++)
                #pragma unroll
                for (int nj = 0; nj < NJ; nj++) {
                    asm volatile(
                        "mma.sync.aligned.m16n8k16.row.col.f32.f16.f16.f32 "
                        "{%0,%1,%2,%3}, {%4,%5,%6,%7}, {%8,%9}, {%0,%1,%2,%3};\n"
                        : "+f"(acc[mi][nj][0]), "+f"(acc[mi][nj][1]),
                          "+f"(acc[mi][nj][2]), "+f"(acc[mi][nj][3])
                        : "r"(a[mi][0]), "r"(a[mi][1]), "r"(a[mi][2]), "r"(a[mi][3]),
                          "r"(b[nj][0]), "r"(b[nj][1]));
                }
            // interleaved next-stage loads hide under tensor execution
            if (do_load) {
                #pragma unroll
                for (int i = ks * CPS; i < (ks + 1) * CPS && i < CPT; i++)
                    load_chunk(sl, kt + 2, i);
            }
        }
        // exactly one commit per iteration (holds loaded chunks, or empty)
        asm volatile("cp.async.commit_group;\n" ::: "memory");

        s  = (s  == NSTAGE - 1) ? 0 : s + 1;
        sl = (sl == NSTAGE - 1) ? 0 : sl + 1;
    }

    // --- epilogue: bias + activation + store ---
    #pragma unroll
    for (int mi = 0; mi < 4; mi++) {
        #pragma unroll
        for (int nj = 0; nj < NJ; nj++) {
            int col = n0 + warp_n * WN + nj * 8 + (lane & 3) * 2;
            #pragma unroll
            for (int h = 0; h < 2; h++) {
                int row = m0 + warp_m * 64 + mi * 16 + (lane >> 2) + h * 8;
                float v0 = acc[mi][nj][h * 2 + 0];
                float v1 = acc[mi][nj][h * 2 + 1];
                if (LAYER == 3) {
                    if (col < NCLS)
                        out[(size_t)row * NCLS + col] = v0 + bias[col];
                    if (col + 1 < NCLS)
                        out[(size_t)row * NCLS + col + 1] = v1 + bias[col + 1];
                } else {
                    __half* __restrict__ H = (LAYER == 1) ? g_H1 : g_H2;
                    float r0 = fmaxf(v0 + bias[col], 0.f);
                    float r1 = fmaxf(v1 + bias[col + 1], 0.f);
                    *reinterpret_cast<__half2*>(&H[(size_t)row * D1 + col]) =
                        __floats2half2_rn(r0, r1);
                }
            }
        }
    }
}

// ---------------------------------------------------------------------------
// Launch
// ---------------------------------------------------------------------------
extern "C" void kernel_launch(void* const* d_in, const int* in_sizes, int n_in,
                              void* d_out, int out_size) {
    const float *X = nullptr, *W0 = nullptr, *b0 = nullptr, *W1 = nullptr,
                *b1 = nullptr, *W2 = nullptr, *b2 = nullptr;
    for (int i = 0; i < n_in; i++) {
        int s = in_sizes[i];
        if      (s == MROWS * D0) X  = (const float*)d_in[i];
        else if (s == D1 * D0)    W0 = (const float*)d_in[i];
        else if (s == D2 * D1)    W1 = (const float*)d_in[i];
        else if (s == NCLS * D2)  W2 = (const float*)d_in[i];
        else if (s == NCLS)       b2 = (const float*)d_in[i];
        else if (s == D1) {
            if (!b0) b0 = (const float*)d_in[i];
            else if (!b1) b1 = (const float*)d_in[i];
        }
    }
    float* out = (float*)d_out;

    const int smem12 = NSTAGE * (BM + 128) * SPAD * 2;   // 110592 B
    const int smem3  = NSTAGE * (BM + 64)  * SPAD * 2;   // 82944 B
    cudaFuncSetAttribute(gemm_mma<1>, cudaFuncAttributeMaxDynamicSharedMemorySize, smem12);
    cudaFuncSetAttribute(gemm_mma<2>, cudaFuncAttributeMaxDynamicSharedMemorySize, smem12);
    cudaFuncSetAttribute(gemm_mma<3>, cudaFuncAttributeMaxDynamicSharedMemorySize, smem3);

    // converts: one fused kernel for X/W0/W1 (16 elems/thread), + w2pad
    {
        long total16 = (long)(NX + NW0 + NW1) / 16;            // 1441792
        int blocks = (int)((total16 + 255) / 256);
        f2h_all_kernel<<<blocks, 256>>>(X, W0, W1);
        int n = NPAD * D2;
        w2pad_kernel<<<(n / 2 + 255) / 256, 256>>>(W2);
    }

    // Layer 1: H1 = relu(X @ W0^T + b0)
    gemm_mma<1><<<dim3(D1 / 128, MROWS / BM), 256, smem12>>>(b0, nullptr);
    // Layer 2: H2 = relu(H1 @ W1^T + b1)
    gemm_mma<2><<<dim3(D2 / 128, MROWS / BM), 256, smem12>>>(b1, nullptr);
    // Layer 3: out = H2 @ W2^T + b2  (N padded to 64, cols >= 51 dropped)
    gemm_mma<3><<<dim3(1, MROWS / BM), 256, smem3>>>(b2, out);
}

// round 17
// speedup vs baseline: 1.0896x; 1.0521x over previous
#include <cuda_runtime.h>
#include <cuda_fp16.h>
#include <cstdint>
#include <cstring>

// ---------------------------------------------------------------------------
// Problem constants (DIMS = [1024, 2048, 2048, 51], B=16, P=1024)
// ---------------------------------------------------------------------------
#define MROWS 16384
#define D0    1024
#define D1    2048
#define D2    2048
#define NCLS  51
#define NPAD  64

#define NX  (MROWS * D0)   // 16777216
#define NW0 (D1 * D0)      // 2097152
#define NW1 (D2 * D1)      // 4194304

// ---------------------------------------------------------------------------
// Device-global scratch (allocation-free rule)
// ---------------------------------------------------------------------------
__device__ __half g_Xh [NX];                  // 32 MB
__device__ __half g_W0h[NW0];                 //  4 MB
__device__ __half g_W1h[NW1];                 //  8 MB
__device__ __half g_W2h[NPAD * D2];           // 256 KB (rows 51..63 zero)
__device__ __half g_H1 [(size_t)MROWS * D1];  // 64 MB
__device__ __half g_H2 [(size_t)MROWS * D2];  // 64 MB

__device__ __forceinline__ unsigned smem_u32(const void* p) {
    return (unsigned)__cvta_generic_to_shared(p);
}

// ---------------------------------------------------------------------------
// Fused fp32->fp16 convert for X, W0, W1 in ONE kernel (kills launch gaps)
// using R14's PROVEN 8-elem pattern: 2x contiguous float4 loads -> 1x 16B
// store per thread. Region select by chunk id; sizes are multiples of 8.
// ---------------------------------------------------------------------------
struct __align__(16) Half8 { __half2 a, b, c, d; };

__global__ void f2h_all_kernel(const float* __restrict__ X,
                               const float* __restrict__ W0,
                               const float* __restrict__ W1) {
    const int t = blockIdx.x * blockDim.x + threadIdx.x;
    long i = (long)t * 8;
    const float* __restrict__ src;
    __half* __restrict__ dst;
    if (i < NX) {
        src = X; dst = g_Xh;
    } else if (i < NX + NW0) {
        src = W0; dst = g_W0h; i -= NX;
    } else if (i < (long)NX + NW0 + NW1) {
        src = W1; dst = g_W1h; i -= ((long)NX + NW0);
    } else {
        return;
    }
    float4 v0 = *reinterpret_cast<const float4*>(src + i);
    float4 v1 = *reinterpret_cast<const float4*>(src + i + 4);
    Half8 o;
    o.a = __floats2half2_rn(v0.x, v0.y);
    o.b = __floats2half2_rn(v0.z, v0.w);
    o.c = __floats2half2_rn(v1.x, v1.y);
    o.d = __floats2half2_rn(v1.z, v1.w);
    *reinterpret_cast<Half8*>(dst + i) = o;
}

// W2 [51,2048] fp32 -> g_W2h [64,2048] fp16, rows 51..63 zeroed
__global__ void w2pad_kernel(const float* __restrict__ W2) {
    int i = (blockIdx.x * blockDim.x + threadIdx.x) * 2;
    if (i < NPAD * D2) {
        int row = i / D2;
        float a = 0.f, b = 0.f;
        if (row < NCLS) {
            a = W2[(size_t)row * D2 + (i % D2)];
            b = W2[(size_t)row * D2 + (i % D2) + 1];
        }
        *reinterpret_cast<__half2*>(&g_W2h[i]) = __floats2half2_rn(a, b);
    }
}

// ---------------------------------------------------------------------------
// fp16 mma.sync GEMM, 3-stage cp.async pipeline, BK=64, fused bias (+relu).
//   C[m,n] = act( sum_k A[m,k] * W[n,k] + bias[n] )
// 256 threads = 8 warps (2 M x 4 N).
//   LAYER 1/2: CTA 128 x 128, warp 64 x 32, occ 2   (R14 empirical optimum)
//   LAYER 3  : CTA  64 x 64,  warp 32 x 16 -> 256 CTAs (better SM fill)
// Next-stage cp.async chunks are INTERLEAVED between the four k16 MMA groups
// so the first ldmatrix is never blocked by an LSU burst, yet loads enter
// flight well before the iteration ends. One commit per iteration (empty at
// the tail) keeps wait_group semantics exact.
// ---------------------------------------------------------------------------
#define BK     64
#define SPAD   72       // halfs per smem row (144B stride; conflict-free LDSM)
#define NSTAGE 3

template<int LAYER>
__global__ void __launch_bounds__(256, 2)
gemm_mma(const float* __restrict__ bias, float* __restrict__ out) {
    constexpr int K  = (LAYER == 1) ? D0 : D1;
    constexpr int BM = (LAYER == 3) ? 64 : 128;
    constexpr int BN = (LAYER == 3) ? 64 : 128;
    constexpr int WM = BM / 2;             // warp M tile: 64 or 32
    constexpr int MI = WM / 16;            // mma count in M: 4 or 2
    constexpr int WN = BN / 4;             // warp N tile: 32 or 16
    constexpr int NJ = WN / 8;             // mma count in N: 4 or 2
    constexpr int NB = WN / 16;            // B ldmatrix.x4 count: 2 or 1
    constexpr int KT = K / BK;
    constexpr int STAGE_H = (BM + BN) * SPAD;      // halfs per stage
    constexpr int CPT = (BM + BN) * 8 / 256;       // 16B chunks per thread (8 or 4)
    constexpr int CPS = (CPT + 3) / 4;             // chunks per k16 step

    const __half* __restrict__ A = (LAYER == 1) ? g_Xh : (LAYER == 2) ? g_H1 : g_H2;
    const __half* __restrict__ W = (LAYER == 1) ? g_W0h : (LAYER == 2) ? g_W1h : g_W2h;

    extern __shared__ __half smem[];

    const int tid  = threadIdx.x;
    const int lane = tid & 31;
    const int wid  = tid >> 5;
    const int warp_m = wid & 1;
    const int warp_n = wid >> 1;
    const int m0 = blockIdx.y * BM;
    const int n0 = blockIdx.x * BN;

    float acc[MI][NJ][4];
    #pragma unroll
    for (int mi = 0; mi < MI; mi++)
        #pragma unroll
        for (int nj = 0; nj < NJ; nj++)
            #pragma unroll
            for (int c = 0; c < 4; c++) acc[mi][nj][c] = 0.f;

    // --- single-chunk issuer (16B cp.async), chunk id = tid + i*256 ---
    auto load_chunk = [&](int s, int kt, int i) {
        const int k0 = kt * BK;
        __half* dst = smem + s * STAGE_H;
        int idx = tid + i * 256;
        int row = idx >> 3;             // 0..BM+BN-1 (8 chunks per 128B row)
        int ch  = idx & 7;
        const __half* src;
        __half* d;
        if (row < BM) {
            src = A + (size_t)(m0 + row) * K + k0 + ch * 8;
            d   = dst + row * SPAD + ch * 8;
        } else {
            int r = row - BM;
            src = W + (size_t)(n0 + r) * K + k0 + ch * 8;
            d   = dst + (BM + r) * SPAD + ch * 8;
        }
        asm volatile("cp.async.cg.shared.global [%0], [%1], 16;\n"
                     :: "r"(smem_u32(d)), "l"(src));
    };

    auto load_stage = [&](int s, int kt) {
        #pragma unroll
        for (int i = 0; i < CPT; i++) load_chunk(s, kt, i);
        asm volatile("cp.async.commit_group;\n" ::: "memory");
    };

    // prologue: fill 2 stages (groups G0, G1)
    load_stage(0, 0);
    load_stage(1, 1);

    int s = 0;           // stage being consumed (kt % 3)
    int sl = 2;          // stage to load this iteration ((kt+2) % 3)
    for (int kt = 0; kt < KT; kt++) {
        // one group per iteration -> keeping <=1 pending retires G(kt) = stage s
        asm volatile("cp.async.wait_group 1;\n" ::: "memory");
        __syncthreads();

        const bool do_load = (kt + 2 < KT);
        const __half* sA = smem + s * STAGE_H;
        const __half* sB = sA + BM * SPAD;

        #pragma unroll
        for (int ks = 0; ks < 4; ks++) {
            const int k16 = ks * 16;
            unsigned a[MI][4];
            #pragma unroll
            for (int mi = 0; mi < MI; mi++) {
                int row = warp_m * WM + mi * 16 + (lane & 15);
                int kh  = k16 + ((lane & 16) ? 8 : 0);
                asm volatile(
                    "ldmatrix.sync.aligned.m8n8.x4.shared.b16 {%0,%1,%2,%3}, [%4];\n"
                    : "=r"(a[mi][0]), "=r"(a[mi][1]), "=r"(a[mi][2]), "=r"(a[mi][3])
                    : "r"(smem_u32(&sA[row * SPAD + kh])));
            }
            unsigned b[NJ][2];
            #pragma unroll
            for (int ni = 0; ni < NB; ni++) {
                int nrow = warp_n * WN + ni * 16 + ((lane & 16) ? 8 : 0) + (lane & 7);
                int kh   = k16 + ((lane & 8) ? 8 : 0);
                unsigned r0, r1, r2, r3;
                asm volatile(
                    "ldmatrix.sync.aligned.m8n8.x4.shared.b16 {%0,%1,%2,%3}, [%4];\n"
                    : "=r"(r0), "=r"(r1), "=r"(r2), "=r"(r3)
                    : "r"(smem_u32(&sB[nrow * SPAD + kh])));
                b[ni * 2 + 0][0] = r0; b[ni * 2 + 0][1] = r1;
                b[ni * 2 + 1][0] = r2; b[ni * 2 + 1][1] = r3;
            }
            #pragma unroll
            for (int mi = 0; mi < MI; mi++)
                #pragma unroll
                for (int nj = 0; nj < NJ; nj++) {
                    asm volatile(
                        "mma.sync.aligned.m16n8k16.row.col.f32.f16.f16.f32 "
                        "{%0,%1,%2,%3}, {%4,%5,%6,%7}, {%8,%9}, {%0,%1,%2,%3};\n"
                        : "+f"(acc[mi][nj][0]), "+f"(acc[mi][nj][1]),
                          "+f"(acc[mi][nj][2]), "+f"(acc[mi][nj][3])
                        : "r"(a[mi][0]), "r"(a[mi][1]), "r"(a[mi][2]), "r"(a[mi][3]),
                          "r"(b[nj][0]), "r"(b[nj][1]));
                }
            // interleaved next-stage loads hide under tensor execution
            if (do_load) {
                #pragma unroll
                for (int i = ks * CPS; i < (ks + 1) * CPS && i < CPT; i++)
                    load_chunk(sl, kt + 2, i);
            }
        }
        // exactly one commit per iteration (holds loaded chunks, or empty)
        asm volatile("cp.async.commit_group;\n" ::: "memory");

        s  = (s  == NSTAGE - 1) ? 0 : s + 1;
        sl = (sl == NSTAGE - 1) ? 0 : sl + 1;
    }

    // --- epilogue: bias + activation + store ---
    #pragma unroll
    for (int mi = 0; mi < MI; mi++) {
        #pragma unroll
        for (int nj = 0; nj < NJ; nj++) {
            int col = n0 + warp_n * WN + nj * 8 + (lane & 3) * 2;
            #pragma unroll
            for (int h = 0; h < 2; h++) {
                int row = m0 + warp_m * WM + mi * 16 + (lane >> 2) + h * 8;
                float v0 = acc[mi][nj][h * 2 + 0];
                float v1 = acc[mi][nj][h * 2 + 1];
                if (LAYER == 3) {
                    if (col < NCLS)
                        out[(size_t)row * NCLS + col] = v0 + bias[col];
                    if (col + 1 < NCLS)
                        out[(size_t)row * NCLS + col + 1] = v1 + bias[col + 1];
                } else {
                    __half* __restrict__ H = (LAYER == 1) ? g_H1 : g_H2;
                    float r0 = fmaxf(v0 + bias[col], 0.f);
                    float r1 = fmaxf(v1 + bias[col + 1], 0.f);
                    *reinterpret_cast<__half2*>(&H[(size_t)row * D1 + col]) =
                        __floats2half2_rn(r0, r1);
                }
            }
        }
    }
}

// ---------------------------------------------------------------------------
// Launch
// ---------------------------------------------------------------------------
extern "C" void kernel_launch(void* const* d_in, const int* in_sizes, int n_in,
                              void* d_out, int out_size) {
    const float *X = nullptr, *W0 = nullptr, *b0 = nullptr, *W1 = nullptr,
                *b1 = nullptr, *W2 = nullptr, *b2 = nullptr;
    for (int i = 0; i < n_in; i++) {
        int s = in_sizes[i];
        if      (s == MROWS * D0) X  = (const float*)d_in[i];
        else if (s == D1 * D0)    W0 = (const float*)d_in[i];
        else if (s == D2 * D1)    W1 = (const float*)d_in[i];
        else if (s == NCLS * D2)  W2 = (const float*)d_in[i];
        else if (s == NCLS)       b2 = (const float*)d_in[i];
        else if (s == D1) {
            if (!b0) b0 = (const float*)d_in[i];
            else if (!b1) b1 = (const float*)d_in[i];
        }
    }
    float* out = (float*)d_out;

    const int smem12 = NSTAGE * (128 + 128) * SPAD * 2;   // 110592 B
    const int smem3  = NSTAGE * (64 + 64)   * SPAD * 2;   // 55296 B
    cudaFuncSetAttribute(gemm_mma<1>, cudaFuncAttributeMaxDynamicSharedMemorySize, smem12);
    cudaFuncSetAttribute(gemm_mma<2>, cudaFuncAttributeMaxDynamicSharedMemorySize, smem12);
    cudaFuncSetAttribute(gemm_mma<3>, cudaFuncAttributeMaxDynamicSharedMemorySize, smem3);

    // converts: one fused kernel (R14-proven 8-elem pattern) + w2pad
    {
        long total8 = (long)(NX + NW0 + NW1) / 8;
        int blocks = (int)((total8 + 255) / 256);
        f2h_all_kernel<<<blocks, 256>>>(X, W0, W1);
        int n = NPAD * D2;
        w2pad_kernel<<<(n / 2 + 255) / 256, 256>>>(W2);
    }

    // Layer 1: H1 = relu(X @ W0^T + b0)
    gemm_mma<1><<<dim3(D1 / 128, MROWS / 128), 256, smem12>>>(b0, nullptr);
    // Layer 2: H2 = relu(H1 @ W1^T + b1)
    gemm_mma<2><<<dim3(D2 / 128, MROWS / 128), 256, smem12>>>(b1, nullptr);
    // Layer 3: out = H2 @ W2^T + b2  (CTA 64x64 -> 256 CTAs, cols >= 51 dropped)
    gemm_mma<3><<<dim3(1, MROWS / 64), 256, smem3>>>(b2, out);
}